// round 2
// baseline (speedup 1.0000x reference)
#include <cuda_runtime.h>
#include <cuda_bf16.h>

#define NB   8
#define CC   256
#define CQK  32
#define LL   4096

// ---------------- scratch (device globals; no allocation allowed) ----------
__device__ float g_Wt[CC * 320];                 // fused weights, channel-major: Wt[c][o], o: 0-31 q, 32-63 k, 64-319 v
__device__ float g_q [NB * CQK * LL];            // (N, 32, L)
__device__ float g_k [NB * CQK * LL];            // (N, 32, L)
__device__ float g_vT[NB * LL * CC];             // (N, L, 256)  -- transposed V

// ---------------- packed f32x2 helpers -------------------------------------
__device__ __forceinline__ unsigned long long pack2(float a, float b) {
    unsigned long long r;
    asm("mov.b64 %0, {%1, %2};" : "=l"(r) : "f"(a), "f"(b));
    return r;
}
__device__ __forceinline__ void unpack2(unsigned long long v, float& lo, float& hi) {
    asm("mov.b64 {%0, %1}, %2;" : "=f"(lo), "=f"(hi) : "l"(v));
}
__device__ __forceinline__ void ffma2(unsigned long long& d, unsigned long long a, unsigned long long b) {
    asm("fma.rn.f32x2 %0, %1, %2, %0;" : "+l"(d) : "l"(a), "l"(b));
}
__device__ __forceinline__ void fmul2(unsigned long long& d, unsigned long long a) {
    asm("mul.rn.f32x2 %0, %1, %0;" : "+l"(d) : "l"(a));
}

// ---------------- kernel 1: weight transpose --------------------------------
__global__ void wtrans_kernel(const float* __restrict__ Wq,
                              const float* __restrict__ Wk,
                              const float* __restrict__ Wv) {
    int idx = blockIdx.x * 256 + threadIdx.x;   // 320*256 total
    if (idx >= 320 * 256) return;
    int o = idx >> 8;          // 0..319
    int c = idx & 255;
    float v;
    if (o < 32)       v = Wq[o * 256 + c];
    else if (o < 64)  v = Wk[(o - 32) * 256 + c];
    else              v = Wv[(o - 64) * 256 + c];
    g_Wt[c * 320 + o] = v;
}

// ---------------- kernel 2: fused QKV projection -----------------------------
// grid (L/128, N), 256 threads, 128KB dyn smem
__global__ __launch_bounds__(256, 1)
void proj_kernel(const float* __restrict__ x,
                 const float* __restrict__ bq,
                 const float* __restrict__ bk,
                 const float* __restrict__ bv) {
    extern __shared__ float xs[];   // [256][128]
    const int n  = blockIdx.y;
    const int l0 = blockIdx.x * 128;
    const int tid = threadIdx.x;

    // load x tile, coalesced
    const float* xb = x + ((size_t)n << 20) + l0;   // n*256*4096
    #pragma unroll 4
    for (int idx = tid; idx < 256 * 128; idx += 256) {
        int c = idx >> 7, l = idx & 127;
        xs[idx] = xb[(c << 12) + l];
    }
    __syncthreads();

    const int warp = tid >> 5, lane = tid & 31;
    const int lb = lane * 4;

    for (int og = 0; og < 10; og++) {
        const int obase = og * 32 + warp * 4;
        float bias[4];
        #pragma unroll
        for (int r = 0; r < 4; r++) {
            int o = obase + r;
            bias[r] = (o < 32) ? bq[o] : (o < 64) ? bk[o - 32] : bv[o - 64];
        }
        float4 acc0 = make_float4(bias[0], bias[0], bias[0], bias[0]);
        float4 acc1 = make_float4(bias[1], bias[1], bias[1], bias[1]);
        float4 acc2 = make_float4(bias[2], bias[2], bias[2], bias[2]);
        float4 acc3 = make_float4(bias[3], bias[3], bias[3], bias[3]);

        #pragma unroll 4
        for (int c = 0; c < 256; c++) {
            float4 w  = __ldg((const float4*)&g_Wt[c * 320 + obase]);
            float4 xv = *(const float4*)&xs[c * 128 + lb];
            acc0.x += w.x * xv.x; acc0.y += w.x * xv.y; acc0.z += w.x * xv.z; acc0.w += w.x * xv.w;
            acc1.x += w.y * xv.x; acc1.y += w.y * xv.y; acc1.z += w.y * xv.z; acc1.w += w.y * xv.w;
            acc2.x += w.z * xv.x; acc2.y += w.z * xv.y; acc2.z += w.z * xv.z; acc2.w += w.z * xv.w;
            acc3.x += w.w * xv.x; acc3.y += w.w * xv.y; acc3.z += w.w * xv.z; acc3.w += w.w * xv.w;
        }

        float4 acc[4] = {acc0, acc1, acc2, acc3};
        if (obase < 64) {
            float* dst = (obase < 32) ? g_q : g_k;
            int ob = (obase < 32) ? obase : obase - 32;
            #pragma unroll
            for (int r = 0; r < 4; r++) {
                *(float4*)&dst[(((size_t)n * CQK + ob + r) << 12) + l0 + lb] = acc[r];
            }
        } else {
            int vo = obase - 64;
            #pragma unroll
            for (int s = 0; s < 4; s++) {
                float4 vv;
                vv.x = (&acc[0].x)[s]; vv.y = (&acc[1].x)[s];
                vv.z = (&acc[2].x)[s]; vv.w = (&acc[3].x)[s];
                *(float4*)&g_vT[(((size_t)n << 12) + l0 + lb + s) * CC + vo] = vv;
            }
        }
    }
}

// ---------------- kernel 3: fused flash attention ----------------------------
// grid (L/64, N), 256 threads, smem = 25216 floats = 100864 B, 2 CTA/SM
#define SM_Q   0
#define SM_K   2048
#define SM_P   4096          // stride 68
#define SM_V   8448          // stride 260
#define SM_AUX 25088         // [0..63] alpha, [64..127] l

__global__ __launch_bounds__(256, 2)
void attn_kernel(const float* __restrict__ x,
                 const float* __restrict__ gamma,
                 float* __restrict__ out) {
    extern __shared__ float sm[];
    float* q_s = sm + SM_Q;
    float* k_s = sm + SM_K;
    float* p_s = sm + SM_P;
    float* v_s = sm + SM_V;
    float* aux = sm + SM_AUX;

    const int n  = blockIdx.y;
    const int i0 = blockIdx.x * 64;
    const int tid = threadIdx.x;

    // S-phase ids: thread owns i = ti*4+r (r<4), j = tj*4+t (t<4)
    const int ti = tid >> 4, tj = tid & 15;
    // PV-phase ids: warp covers c = w*32..w*32+31; lane: i = ig*8+r (r<8), c = cbase+ 0..7
    const int w = tid >> 5, lane = tid & 31;
    const int ig = lane >> 2, cg = lane & 3;
    const int cbase = w * 32 + cg * 8;

    // load Q tile
    {
        const float* qb = g_q + ((size_t)n * CQK << 12) + i0;
        #pragma unroll
        for (int idx = tid; idx < 2048; idx += 256) {
            int d = idx >> 6, i = idx & 63;
            q_s[idx] = qb[(d << 12) + i];
        }
    }

    float mrun[4], lrun[4];
    #pragma unroll
    for (int r = 0; r < 4; r++) { mrun[r] = -1e30f; lrun[r] = 0.f; }
    unsigned long long O[8][4];
    #pragma unroll
    for (int r = 0; r < 8; r++)
        #pragma unroll
        for (int t = 0; t < 4; t++) O[r][t] = 0ull;

    const float4* q4 = (const float4*)q_s;
    const float4* k4 = (const float4*)k_s;
    const float4* p4 = (const float4*)p_s;
    const unsigned long long* v2 = (const unsigned long long*)v_s;

    for (int jt = 0; jt < 64; jt++) {
        const int j0 = jt * 64;
        __syncthreads();
        // load K tile (32 x 64)
        {
            const float* kb = g_k + ((size_t)n * CQK << 12) + j0;
            #pragma unroll
            for (int idx = tid; idx < 2048; idx += 256) {
                int d = idx >> 6, j = idx & 63;
                k_s[idx] = kb[(d << 12) + j];
            }
        }
        // load V tile (64 x 256), stride 260
        {
            const float4* vb = (const float4*)(g_vT + (((size_t)n << 12) + j0) * CC);
            #pragma unroll
            for (int idx = tid; idx < 4096; idx += 256) {
                int j = idx >> 6, c4 = idx & 63;
                float4 vv = __ldg(&vb[j * 64 + c4]);
                *(float4*)&v_s[j * 260 + c4 * 4] = vv;
            }
        }
        __syncthreads();

        // ---- S = Q^T K (4i x 4j per thread) ----
        float s[4][4];
        #pragma unroll
        for (int r = 0; r < 4; r++)
            #pragma unroll
            for (int t = 0; t < 4; t++) s[r][t] = 0.f;

        #pragma unroll
        for (int d = 0; d < 32; d++) {
            float4 qv = q4[d * 16 + ti];
            float4 kv = k4[d * 16 + tj];
            const float* qp = &qv.x;
            const float* kp = &kv.x;
            #pragma unroll
            for (int r = 0; r < 4; r++)
                #pragma unroll
                for (int t = 0; t < 4; t++) s[r][t] += qp[r] * kp[t];
        }

        // ---- online softmax ----
        #pragma unroll
        for (int r = 0; r < 4; r++) {
            float mx = fmaxf(fmaxf(s[r][0], s[r][1]), fmaxf(s[r][2], s[r][3]));
            #pragma unroll
            for (int off = 8; off >= 1; off >>= 1)
                mx = fmaxf(mx, __shfl_xor_sync(0xffffffffu, mx, off));
            float mn = fmaxf(mrun[r], mx);
            float al = __expf(mrun[r] - mn);
            mrun[r] = mn;
            float rs = 0.f;
            #pragma unroll
            for (int t = 0; t < 4; t++) {
                float p = __expf(s[r][t] - mn);
                s[r][t] = p;
                rs += p;
            }
            #pragma unroll
            for (int off = 8; off >= 1; off >>= 1)
                rs += __shfl_xor_sync(0xffffffffu, rs, off);
            lrun[r] = al * lrun[r] + rs;
            #pragma unroll
            for (int t = 0; t < 4; t++)
                p_s[(tj * 4 + t) * 68 + ti * 4 + r] = s[r][t];
            if (tj == 0) aux[ti * 4 + r] = al;
        }
        __syncthreads();

        // rescale O by alpha (PV i-ownership)
        #pragma unroll
        for (int r = 0; r < 8; r++) {
            float a = aux[ig * 8 + r];
            unsigned long long ap = pack2(a, a);
            #pragma unroll
            for (int t = 0; t < 4; t++) fmul2(O[r][t], ap);
        }

        // ---- O += P V  (packed f32x2) ----
        #pragma unroll 2
        for (int j = 0; j < 64; j++) {
            float4 pA = p4[j * 17 + ig * 2];
            float4 pB = p4[j * 17 + ig * 2 + 1];
            unsigned long long va = v2[j * 130 + (cbase >> 1) + 0];
            unsigned long long vb = v2[j * 130 + (cbase >> 1) + 1];
            unsigned long long vc = v2[j * 130 + (cbase >> 1) + 2];
            unsigned long long vd = v2[j * 130 + (cbase >> 1) + 3];
            float pr[8] = {pA.x, pA.y, pA.z, pA.w, pB.x, pB.y, pB.z, pB.w};
            #pragma unroll
            for (int r = 0; r < 8; r++) {
                unsigned long long pp = pack2(pr[r], pr[r]);
                ffma2(O[r][0], pp, va);
                ffma2(O[r][1], pp, vb);
                ffma2(O[r][2], pp, vc);
                ffma2(O[r][3], pp, vd);
            }
        }
    }

    // publish l, then finalize
    __syncthreads();
    if (tj == 0) {
        #pragma unroll
        for (int r = 0; r < 4; r++) aux[64 + ti * 4 + r] = lrun[r];
    }
    __syncthreads();

    const float g = __ldg(gamma);
    #pragma unroll
    for (int r = 0; r < 8; r++) {
        const int il = ig * 8 + r;
        const float linv = 1.0f / aux[64 + il];
        const int i = i0 + il;
        #pragma unroll
        for (int t = 0; t < 4; t++) {
            float lo, hi;
            unpack2(O[r][t], lo, hi);
            int c0 = cbase + 2 * t;
            size_t idx0 = (((size_t)n * CC + c0) << 12) + i;
            size_t idx1 = idx0 + ((size_t)1 << 12);
            out[idx0] = g * (lo * linv) + x[idx0];
            out[idx1] = g * (hi * linv) + x[idx1];
        }
    }
}

// ---------------- launch ----------------------------------------------------
extern "C" void kernel_launch(void* const* d_in, const int* in_sizes, int n_in,
                              void* d_out, int out_size) {
    const float* x     = (const float*)d_in[0];
    const float* Wq    = (const float*)d_in[1];
    const float* bq    = (const float*)d_in[2];
    const float* Wk    = (const float*)d_in[3];
    const float* bk    = (const float*)d_in[4];
    const float* Wv    = (const float*)d_in[5];
    const float* bv    = (const float*)d_in[6];
    const float* gamma = (const float*)d_in[7];
    float* out = (float*)d_out;

    cudaFuncSetAttribute(proj_kernel, cudaFuncAttributeMaxDynamicSharedMemorySize, 131072);
    cudaFuncSetAttribute(attn_kernel, cudaFuncAttributeMaxDynamicSharedMemorySize, 100864);

    wtrans_kernel<<<(320 * 256 + 255) / 256, 256>>>(Wq, Wk, Wv);
    proj_kernel<<<dim3(LL / 128, NB), 256, 131072>>>(x, bq, bk, bv);
    attn_kernel<<<dim3(LL / 64, NB), 256, 100864>>>(x, gamma, out);
}

// round 4
// speedup vs baseline: 2.2447x; 2.2447x over previous
#include <cuda_runtime.h>
#include <cstdint>

#define NB   8
#define CC   256
#define CQK  32
#define LL   4096
#define BI   64
#define BJ   32
#define NJT  (LL / BJ)          // 128 j-tiles

// ---------------- scratch (device globals) ----------------------------------
__device__ float g_Wt [CC * 320];                 // fused weights, channel-major
__device__ float g_qhi[NB * LL * CQK];            // (N, L, 32) token-major tf32-hi
__device__ float g_qlo[NB * LL * CQK];
__device__ float g_khi[NB * CQK * LL];            // (N, 32, L) k-major tf32-hi
__device__ float g_klo[NB * CQK * LL];
__device__ float g_v  [(size_t)NB * CC * LL];     // (N, C, L) tf32-rounded

// ---------------- helpers ----------------------------------------------------
__device__ __forceinline__ uint32_t smem_u32(const void* p) {
    uint32_t a;
    asm("{ .reg .u64 t; cvta.to.shared.u64 t, %1; cvt.u32.u64 %0, t; }" : "=r"(a) : "l"(p));
    return a;
}
__device__ __forceinline__ float tf32r(float x) {
    uint32_t u;
    asm("cvt.rn.tf32.f32 %0, %1;" : "=r"(u) : "f"(x));
    return __uint_as_float(u);
}
__device__ __forceinline__ void cp_async16(uint32_t dst, const void* src) {
    asm volatile("cp.async.cg.shared.global [%0], [%1], 16;"
                 :: "r"(dst), "l"((unsigned long long)__cvta_generic_to_global(src)) : "memory");
}
#define CP_COMMIT() asm volatile("cp.async.commit_group;" ::: "memory")
#define CP_WAIT0()  asm volatile("cp.async.wait_group 0;" ::: "memory")

// m16n8k8 tf32 mma: D(f32) += A(tf32) * B(tf32)
__device__ __forceinline__ void mma_tf32(float c[4], const uint32_t a[4],
                                         uint32_t b0, uint32_t b1) {
    asm("mma.sync.aligned.m16n8k8.row.col.f32.tf32.tf32.f32 "
        "{%0,%1,%2,%3}, {%4,%5,%6,%7}, {%8,%9}, {%0,%1,%2,%3};"
        : "+f"(c[0]), "+f"(c[1]), "+f"(c[2]), "+f"(c[3])
        : "r"(a[0]), "r"(a[1]), "r"(a[2]), "r"(a[3]), "r"(b0), "r"(b1));
}

// ---------------- kernel 1: weight transpose ---------------------------------
__global__ void wtrans_kernel(const float* __restrict__ Wq,
                              const float* __restrict__ Wk,
                              const float* __restrict__ Wv) {
    int idx = blockIdx.x * 256 + threadIdx.x;
    if (idx >= 320 * 256) return;
    int o = idx >> 8, c = idx & 255;
    float v;
    if (o < 32)       v = Wq[o * 256 + c];
    else if (o < 64)  v = Wk[(o - 32) * 256 + c];
    else              v = Wv[(o - 64) * 256 + c];
    g_Wt[c * 320 + o] = v;
}

// ---------------- kernel 2: fused QKV projection -----------------------------
// grid (L/128, N), 256 threads, 128KB dyn smem
__global__ __launch_bounds__(256, 1)
void proj_kernel(const float* __restrict__ x,
                 const float* __restrict__ bq,
                 const float* __restrict__ bk,
                 const float* __restrict__ bv) {
    extern __shared__ float xs[];   // [256][128]
    const int n  = blockIdx.y;
    const int l0 = blockIdx.x * 128;
    const int tid = threadIdx.x;

    const float* xb = x + ((size_t)n << 20) + l0;
    #pragma unroll 4
    for (int idx = tid; idx < 256 * 128; idx += 256) {
        int c = idx >> 7, l = idx & 127;
        xs[idx] = xb[(c << 12) + l];
    }
    __syncthreads();

    const int warp = tid >> 5, lane = tid & 31;
    const int lb = lane * 4;

    for (int og = 0; og < 10; og++) {
        const int obase = og * 32 + warp * 4;
        float bias[4];
        #pragma unroll
        for (int r = 0; r < 4; r++) {
            int o = obase + r;
            bias[r] = (o < 32) ? bq[o] : (o < 64) ? bk[o - 32] : bv[o - 64];
        }
        float4 acc0 = make_float4(bias[0], bias[0], bias[0], bias[0]);
        float4 acc1 = make_float4(bias[1], bias[1], bias[1], bias[1]);
        float4 acc2 = make_float4(bias[2], bias[2], bias[2], bias[2]);
        float4 acc3 = make_float4(bias[3], bias[3], bias[3], bias[3]);

        #pragma unroll 4
        for (int c = 0; c < 256; c++) {
            float4 w  = __ldg((const float4*)&g_Wt[c * 320 + obase]);
            float4 xv = *(const float4*)&xs[c * 128 + lb];
            acc0.x += w.x * xv.x; acc0.y += w.x * xv.y; acc0.z += w.x * xv.z; acc0.w += w.x * xv.w;
            acc1.x += w.y * xv.x; acc1.y += w.y * xv.y; acc1.z += w.y * xv.z; acc1.w += w.y * xv.w;
            acc2.x += w.z * xv.x; acc2.y += w.z * xv.y; acc2.z += w.z * xv.z; acc2.w += w.z * xv.w;
            acc3.x += w.w * xv.x; acc3.y += w.w * xv.y; acc3.z += w.w * xv.z; acc3.w += w.w * xv.w;
        }
        float4 acc[4] = {acc0, acc1, acc2, acc3};

        if (obase < 32) {
            // Q: token-major (N, L, 32), hi/lo split
            int ob = obase;
            #pragma unroll
            for (int s = 0; s < 4; s++) {
                float v0 = (&acc[0].x)[s], v1 = (&acc[1].x)[s];
                float v2 = (&acc[2].x)[s], v3 = (&acc[3].x)[s];
                float h0 = tf32r(v0), h1 = tf32r(v1), h2 = tf32r(v2), h3 = tf32r(v3);
                float e0 = tf32r(v0 - h0), e1 = tf32r(v1 - h1);
                float e2 = tf32r(v2 - h2), e3 = tf32r(v3 - h3);
                size_t base = ((size_t)(n << 12) + l0 + lb + s) * 32 + ob;
                *(float4*)&g_qhi[base] = make_float4(h0, h1, h2, h3);
                *(float4*)&g_qlo[base] = make_float4(e0, e1, e2, e3);
            }
        } else if (obase < 64) {
            // K: k-major (N, 32, L), hi/lo split
            int ob = obase - 32;
            #pragma unroll
            for (int r = 0; r < 4; r++) {
                float4 a = acc[r];
                float4 h = make_float4(tf32r(a.x), tf32r(a.y), tf32r(a.z), tf32r(a.w));
                float4 e = make_float4(tf32r(a.x - h.x), tf32r(a.y - h.y),
                                       tf32r(a.z - h.z), tf32r(a.w - h.w));
                size_t base = (((size_t)n * 32 + ob + r) << 12) + l0 + lb;
                *(float4*)&g_khi[base] = h;
                *(float4*)&g_klo[base] = e;
            }
        } else {
            int vo = obase - 64;
            #pragma unroll
            for (int r = 0; r < 4; r++) {
                float4 a = acc[r];
                a.x = tf32r(a.x); a.y = tf32r(a.y); a.z = tf32r(a.z); a.w = tf32r(a.w);
                *(float4*)&g_v[(((size_t)n * CC + vo + r) << 12) + l0 + lb] = a;
            }
        }
    }
}

// ---------------- kernel 3: tf32 mma.sync flash attention --------------------
// SMEM layout (bytes); all tile rows padded to stride 36 floats (144B) ->
// fragment LDS are bank-conflict-free (verified: bank = (4m+g+const)%32 perm).
#define OFF_QHI 0           // [64][36] f32
#define OFF_QLO 9216
#define OFF_K   18432       // buf b at +b*9216: [KHI 32][36] then [KLO 32][36]
#define OFF_V   36864       // buf b at +b*36864: [256][36]
#define ATTN_SMEM 110592

__device__ __forceinline__ void load_tile(char* sm, int n, int j0, int buf, int tid) {
    const uint32_t kbase = smem_u32(sm) + OFF_K + buf * 9216;
    #pragma unroll
    for (int it = 0; it < 4; it++) {
        int c  = it * 128 + tid;        // 0..511
        int hl = c >> 8;
        int k  = (c >> 3) & 31;
        int s  = c & 7;
        const float* src = (hl ? g_klo : g_khi) + ((((size_t)n * 32 + k) << 12) + j0 + s * 4);
        cp_async16(kbase + hl * 4608 + k * 144 + s * 16, src);
    }
    const uint32_t vbase = smem_u32(sm) + OFF_V + buf * 36864;
    #pragma unroll
    for (int it = 0; it < 16; it++) {
        int c  = it * 128 + tid;        // 0..2047
        int cr = c >> 3;
        int s  = c & 7;
        const float* src = g_v + ((((size_t)n * CC + cr) << 12) + j0 + s * 4);
        cp_async16(vbase + cr * 144 + s * 16, src);
    }
}

__global__ __launch_bounds__(128, 2)
void attn_kernel(const float* __restrict__ x,
                 const float* __restrict__ gamma,
                 float* __restrict__ out) {
    extern __shared__ char sm[];
    const int tid  = threadIdx.x;
    const int wid  = tid >> 5, lane = tid & 31;
    const int g    = lane >> 2, m = lane & 3;
    const int iw   = wid * 16;                  // warp's row base within tile
    const int n    = blockIdx.y;
    const int i0   = blockIdx.x * BI;

    // ---- prologue: Q tiles (plain), K/V tile 0 (cp.async) ----
    {
        float* smf = (float*)sm;
        #pragma unroll
        for (int it = 0; it < 8; it++) {
            int idx  = it * 128 + tid;          // 0..1023
            int half = idx >> 9;                // 0 hi, 1 lo
            int r    = (idx >> 3) & 63;
            int s    = idx & 7;
            const float* src = (half ? g_qlo : g_qhi) + ((size_t)((n << 12) + i0 + r)) * 32 + s * 4;
            float4 v = __ldg((const float4*)src);
            *(float4*)((char*)smf + (half ? OFF_QLO : OFF_QHI) + r * 144 + s * 16) = v;
        }
    }
    load_tile(sm, n, 0, 0, tid);
    CP_COMMIT();

    // ---- persistent state ----
    const uint32_t* QH = (const uint32_t*)(sm + OFF_QHI);
    const uint32_t* QL = (const uint32_t*)(sm + OFF_QLO);
    uint32_t qh[4][4];
    float O[32][4];
    #pragma unroll
    for (int nt = 0; nt < 32; nt++)
        #pragma unroll
        for (int e = 0; e < 4; e++) O[nt][e] = 0.f;
    float lrun0 = 0.f, lrun1 = 0.f;

    const int srcA = (lane & ~3) | (m >> 1);
    const int srcB = srcA + 2;

    for (int jt = 0; jt < NJT; jt++) {
        const int cur = jt & 1;
        CP_WAIT0();
        __syncthreads();
        if (jt + 1 < NJT) { load_tile(sm, n, (jt + 1) * BJ, 1 - cur, tid); CP_COMMIT(); }

        const uint32_t* KH = (const uint32_t*)(sm + OFF_K + cur * 9216);
        const uint32_t* KL = KH + 1152;
        const uint32_t* VS = (const uint32_t*)(sm + OFF_V + cur * 36864);

        // Q fragments for this warp (qh persistent-ish, ql per-tile)
        uint32_t ql[4][4];
        #pragma unroll
        for (int kc = 0; kc < 4; kc++) {
            qh[kc][0] = QH[(iw + g)     * 36 + 8 * kc + m];
            qh[kc][1] = QH[(iw + g + 8) * 36 + 8 * kc + m];
            qh[kc][2] = QH[(iw + g)     * 36 + 8 * kc + m + 4];
            qh[kc][3] = QH[(iw + g + 8) * 36 + 8 * kc + m + 4];
            ql[kc][0] = QL[(iw + g)     * 36 + 8 * kc + m];
            ql[kc][1] = QL[(iw + g + 8) * 36 + 8 * kc + m];
            ql[kc][2] = QL[(iw + g)     * 36 + 8 * kc + m + 4];
            ql[kc][3] = QL[(iw + g + 8) * 36 + 8 * kc + m + 4];
        }

        // ---- S = Q K^T, 3xTF32 ----
        float C[4][4];
        #pragma unroll
        for (int nt = 0; nt < 4; nt++) {
            #pragma unroll
            for (int e = 0; e < 4; e++) C[nt][e] = 0.f;
            #pragma unroll
            for (int kc = 0; kc < 4; kc++) {
                uint32_t kb0 = KH[(8 * kc + m)     * 36 + 8 * nt + g];
                uint32_t kb1 = KH[(8 * kc + m + 4) * 36 + 8 * nt + g];
                mma_tf32(C[nt], qh[kc], kb0, kb1);
                mma_tf32(C[nt], ql[kc], kb0, kb1);
                uint32_t lb0 = KL[(8 * kc + m)     * 36 + 8 * nt + g];
                uint32_t lb1 = KL[(8 * kc + m + 4) * 36 + 8 * nt + g];
                mma_tf32(C[nt], qh[kc], lb0, lb1);
            }
        }

        // ---- softmax (no max-sub; S bounded) + tf32-round P ----
        float rs0 = 0.f, rs1 = 0.f;
        #pragma unroll
        for (int nt = 0; nt < 4; nt++) {
            float p0 = tf32r(__expf(C[nt][0])); rs0 += p0; C[nt][0] = p0;
            float p1 = tf32r(__expf(C[nt][1])); rs0 += p1; C[nt][1] = p1;
            float p2 = tf32r(__expf(C[nt][2])); rs1 += p2; C[nt][2] = p2;
            float p3 = tf32r(__expf(C[nt][3])); rs1 += p3; C[nt][3] = p3;
        }
        rs0 += __shfl_xor_sync(0xffffffffu, rs0, 1);
        rs0 += __shfl_xor_sync(0xffffffffu, rs0, 2);
        rs1 += __shfl_xor_sync(0xffffffffu, rs1, 1);
        rs1 += __shfl_xor_sync(0xffffffffu, rs1, 2);
        lrun0 += rs0; lrun1 += rs1;

        // ---- relayout P: C-frag -> A-frag (in-warp shuffles) ----
        uint32_t pa[4][4];
        #pragma unroll
        for (int kc = 0; kc < 4; kc++) {
            float v0, v1;
            v0 = __shfl_sync(0xffffffffu, C[kc][0], srcA);
            v1 = __shfl_sync(0xffffffffu, C[kc][1], srcA);
            pa[kc][0] = __float_as_uint((m & 1) ? v1 : v0);
            v0 = __shfl_sync(0xffffffffu, C[kc][2], srcA);
            v1 = __shfl_sync(0xffffffffu, C[kc][3], srcA);
            pa[kc][1] = __float_as_uint((m & 1) ? v1 : v0);
            v0 = __shfl_sync(0xffffffffu, C[kc][0], srcB);
            v1 = __shfl_sync(0xffffffffu, C[kc][1], srcB);
            pa[kc][2] = __float_as_uint((m & 1) ? v1 : v0);
            v0 = __shfl_sync(0xffffffffu, C[kc][2], srcB);
            v1 = __shfl_sync(0xffffffffu, C[kc][3], srcB);
            pa[kc][3] = __float_as_uint((m & 1) ? v1 : v0);
        }

        // ---- O += P * V ----
        #pragma unroll
        for (int kc = 0; kc < 4; kc++) {
            #pragma unroll
            for (int nt = 0; nt < 32; nt++) {
                uint32_t vb0 = VS[(8 * nt + g) * 36 + 8 * kc + m];
                uint32_t vb1 = VS[(8 * nt + g) * 36 + 8 * kc + m + 4];
                mma_tf32(O[nt], pa[kc], vb0, vb1);
            }
        }
    }

    // ---- epilogue ----
    const float linv0 = 1.0f / lrun0;
    const float linv1 = 1.0f / lrun1;
    const float gam = __ldg(gamma);
    #pragma unroll
    for (int nt = 0; nt < 32; nt++) {
        #pragma unroll
        for (int e = 0; e < 4; e++) {
            int c   = 8 * nt + 2 * m + (e & 1);
            int row = iw + g + 8 * (e >> 1);
            size_t idx = (((size_t)(n * CC + c)) << 12) + i0 + row;
            float o = O[nt][e] * ((e >> 1) ? linv1 : linv0);
            out[idx] = gam * o + __ldg(&x[idx]);
        }
    }
}

// ---------------- launch -----------------------------------------------------
extern "C" void kernel_launch(void* const* d_in, const int* in_sizes, int n_in,
                              void* d_out, int out_size) {
    const float* x     = (const float*)d_in[0];
    const float* Wq    = (const float*)d_in[1];
    const float* bq    = (const float*)d_in[2];
    const float* Wk    = (const float*)d_in[3];
    const float* bk    = (const float*)d_in[4];
    const float* Wv    = (const float*)d_in[5];
    const float* bv    = (const float*)d_in[6];
    const float* gamma = (const float*)d_in[7];
    float* out = (float*)d_out;

    cudaFuncSetAttribute(proj_kernel, cudaFuncAttributeMaxDynamicSharedMemorySize, 131072);
    cudaFuncSetAttribute(attn_kernel, cudaFuncAttributeMaxDynamicSharedMemorySize, ATTN_SMEM);

    wtrans_kernel<<<(320 * 256 + 255) / 256, 256>>>(Wq, Wk, Wv);
    proj_kernel<<<dim3(LL / 128, NB), 256, 131072>>>(x, bq, bk, bv);
    attn_kernel<<<dim3(LL / BI, NB), 128, ATTN_SMEM>>>(x, gamma, out);
}

// round 5
// speedup vs baseline: 2.8664x; 1.2770x over previous
#include <cuda_runtime.h>
#include <cuda_fp16.h>
#include <cstdint>

#define NB   8
#define CC   256
#define CQK  32
#define LL   4096
#define BI   64
#define BJ   32
#define NJT  (LL / BJ)          // 128 j-tiles

// ---------------- scratch (device globals) ----------------------------------
__device__ float  g_Wt [CC * 320];                  // fused weights, channel-major
__device__ __half g_qh [NB * LL * CQK];             // (N, L, 32) token-major fp16-hi
__device__ __half g_ql [NB * LL * CQK];
__device__ __half g_kh [NB * LL * CQK];             // (N, L, 32) token-major fp16-hi
__device__ __half g_kl [NB * LL * CQK];
__device__ __half g_v  [(size_t)NB * CC * LL];      // (N, C, L) fp16, l contiguous

// ---------------- helpers ----------------------------------------------------
__device__ __forceinline__ uint32_t smem_u32(const void* p) {
    uint32_t a;
    asm("{ .reg .u64 t; cvta.to.shared.u64 t, %1; cvt.u32.u64 %0, t; }" : "=r"(a) : "l"(p));
    return a;
}
__device__ __forceinline__ void cp_async16(uint32_t dst, const void* src) {
    asm volatile("cp.async.cg.shared.global [%0], [%1], 16;"
                 :: "r"(dst), "l"((unsigned long long)__cvta_generic_to_global(src)) : "memory");
}
#define CP_COMMIT() asm volatile("cp.async.commit_group;" ::: "memory")
#define CP_WAIT0()  asm volatile("cp.async.wait_group 0;" ::: "memory")

__device__ __forceinline__ uint32_t h2u(__half2 h) { return *reinterpret_cast<uint32_t*>(&h); }

// m16n8k16 fp16 mma: D(f32) += A(f16) * B(f16)
__device__ __forceinline__ void mma_f16(float c[4], const uint32_t a[4],
                                        uint32_t b0, uint32_t b1) {
    asm("mma.sync.aligned.m16n8k16.row.col.f32.f16.f16.f32 "
        "{%0,%1,%2,%3}, {%4,%5,%6,%7}, {%8,%9}, {%0,%1,%2,%3};"
        : "+f"(c[0]), "+f"(c[1]), "+f"(c[2]), "+f"(c[3])
        : "r"(a[0]), "r"(a[1]), "r"(a[2]), "r"(a[3]), "r"(b0), "r"(b1));
}

// ---------------- kernel 1: weight transpose ---------------------------------
__global__ void wtrans_kernel(const float* __restrict__ Wq,
                              const float* __restrict__ Wk,
                              const float* __restrict__ Wv) {
    int idx = blockIdx.x * 256 + threadIdx.x;
    if (idx >= 320 * 256) return;
    int o = idx >> 8, c = idx & 255;
    float v;
    if (o < 32)       v = Wq[o * 256 + c];
    else if (o < 64)  v = Wk[(o - 32) * 256 + c];
    else              v = Wv[(o - 64) * 256 + c];
    g_Wt[c * 320 + o] = v;
}

// ---------------- kernel 2: fused QKV projection -----------------------------
// grid (L/128, N), 256 threads, 128KB dyn smem
__global__ __launch_bounds__(256, 1)
void proj_kernel(const float* __restrict__ x,
                 const float* __restrict__ bq,
                 const float* __restrict__ bk,
                 const float* __restrict__ bv) {
    extern __shared__ float xs[];   // [256][128]
    const int n  = blockIdx.y;
    const int l0 = blockIdx.x * 128;
    const int tid = threadIdx.x;

    const float* xb = x + ((size_t)n << 20) + l0;
    #pragma unroll 4
    for (int idx = tid; idx < 256 * 128; idx += 256) {
        int c = idx >> 7, l = idx & 127;
        xs[idx] = xb[(c << 12) + l];
    }
    __syncthreads();

    const int warp = tid >> 5, lane = tid & 31;
    const int lb = lane * 4;

    for (int og = 0; og < 10; og++) {
        const int obase = og * 32 + warp * 4;
        float bias[4];
        #pragma unroll
        for (int r = 0; r < 4; r++) {
            int o = obase + r;
            bias[r] = (o < 32) ? bq[o] : (o < 64) ? bk[o - 32] : bv[o - 64];
        }
        float4 acc0 = make_float4(bias[0], bias[0], bias[0], bias[0]);
        float4 acc1 = make_float4(bias[1], bias[1], bias[1], bias[1]);
        float4 acc2 = make_float4(bias[2], bias[2], bias[2], bias[2]);
        float4 acc3 = make_float4(bias[3], bias[3], bias[3], bias[3]);

        #pragma unroll 4
        for (int c = 0; c < 256; c++) {
            float4 w  = __ldg((const float4*)&g_Wt[c * 320 + obase]);
            float4 xv = *(const float4*)&xs[c * 128 + lb];
            acc0.x += w.x * xv.x; acc0.y += w.x * xv.y; acc0.z += w.x * xv.z; acc0.w += w.x * xv.w;
            acc1.x += w.y * xv.x; acc1.y += w.y * xv.y; acc1.z += w.y * xv.z; acc1.w += w.y * xv.w;
            acc2.x += w.z * xv.x; acc2.y += w.z * xv.y; acc2.z += w.z * xv.z; acc2.w += w.z * xv.w;
            acc3.x += w.w * xv.x; acc3.y += w.w * xv.y; acc3.z += w.w * xv.z; acc3.w += w.w * xv.w;
        }
        float4 acc[4] = {acc0, acc1, acc2, acc3};

        if (obase < 64) {
            // Q / K: token-major (N, L, 32), fp16 hi/lo split
            __half* dsth = (obase < 32) ? g_qh : g_kh;
            __half* dstl = (obase < 32) ? g_ql : g_kl;
            const int ob = obase & 31;
            #pragma unroll
            for (int s = 0; s < 4; s++) {
                float v0 = (&acc[0].x)[s], v1 = (&acc[1].x)[s];
                float v2 = (&acc[2].x)[s], v3 = (&acc[3].x)[s];
                __half h0 = __float2half_rn(v0), h1 = __float2half_rn(v1);
                __half h2 = __float2half_rn(v2), h3 = __float2half_rn(v3);
                __half e0 = __float2half_rn(v0 - __half2float(h0));
                __half e1 = __float2half_rn(v1 - __half2float(h1));
                __half e2 = __float2half_rn(v2 - __half2float(h2));
                __half e3 = __float2half_rn(v3 - __half2float(h3));
                size_t base = ((size_t)((n << 12) + l0 + lb + s)) * 32 + ob;
                ((__half2*)(dsth + base))[0] = __halves2half2(h0, h1);
                ((__half2*)(dsth + base))[1] = __halves2half2(h2, h3);
                ((__half2*)(dstl + base))[0] = __halves2half2(e0, e1);
                ((__half2*)(dstl + base))[1] = __halves2half2(e2, e3);
            }
        } else {
            const int vo = obase - 64;
            #pragma unroll
            for (int r = 0; r < 4; r++) {
                float4 a = acc[r];
                size_t base = (((size_t)n * CC + vo + r) << 12) + l0 + lb;
                ((__half2*)(g_v + base))[0] = __floats2half2_rn(a.x, a.y);
                ((__half2*)(g_v + base))[1] = __floats2half2_rn(a.z, a.w);
            }
        }
    }
}

// ---------------- kernel 3: fp16 mma.sync flash attention --------------------
// Rows padded to 40 fp16 (80 B): fragment 32-bit LDS are conflict-free
// (bank = (20g + m + 8kc) % 32 is a permutation over the 32 lanes).
#define OFF_QH 0            // [64][40] fp16
#define OFF_QL 5120
#define OFF_K  10240        // buf b at +b*5120: [KH 32][40] then [KL 32][40]
#define OFF_V  20480        // buf b at +b*20480: [256][40] fp16
#define ATTN_SMEM 61440

__device__ __forceinline__ void load_tile(char* sm, int n, int j0, int buf, int tid) {
    const uint32_t kbase = smem_u32(sm) + OFF_K + buf * 5120;
    #pragma unroll
    for (int it = 0; it < 2; it++) {
        int idx = it * 128 + tid;        // 0..255
        int hl = idx >> 7;
        int r  = (idx >> 2) & 31;
        int s  = idx & 3;
        const __half* src = (hl ? g_kl : g_kh) + ((size_t)((n << 12) + j0 + r)) * 32 + s * 8;
        cp_async16(kbase + hl * 2560 + r * 80 + s * 16, src);
    }
    const uint32_t vbase = smem_u32(sm) + OFF_V + buf * 20480;
    #pragma unroll
    for (int it = 0; it < 8; it++) {
        int idx = it * 128 + tid;        // 0..1023
        int cr = idx >> 2;
        int s  = idx & 3;
        const __half* src = g_v + (((size_t)n * CC + cr) << 12) + j0 + s * 8;
        cp_async16(vbase + cr * 80 + s * 16, src);
    }
}

__global__ __launch_bounds__(128, 2)
void attn_kernel(const float* __restrict__ x,
                 const float* __restrict__ gamma,
                 float* __restrict__ out) {
    extern __shared__ char sm[];
    const int tid  = threadIdx.x;
    const int wid  = tid >> 5, lane = tid & 31;
    const int g    = lane >> 2, m = lane & 3;
    const int iw   = wid * 16;
    const int n    = blockIdx.y;
    const int i0   = blockIdx.x * BI;

    // ---- prologue: Q (hi/lo) + K/V tile 0 via cp.async ----
    {
        const uint32_t smb = smem_u32(sm);
        #pragma unroll
        for (int it = 0; it < 4; it++) {
            int idx  = it * 128 + tid;          // 0..511
            int half = idx >> 8;
            int r    = (idx >> 2) & 63;
            int s    = idx & 3;
            const __half* src = (half ? g_ql : g_qh) + ((size_t)((n << 12) + i0 + r)) * 32 + s * 8;
            cp_async16(smb + (half ? OFF_QL : OFF_QH) + r * 80 + s * 16, src);
        }
    }
    load_tile(sm, n, 0, 0, tid);
    CP_COMMIT();

    const uint32_t* QHw = (const uint32_t*)(sm + OFF_QH);
    const uint32_t* QLw = (const uint32_t*)(sm + OFF_QL);
    uint32_t qh[2][4], ql[2][4];

    float O[32][4];
    #pragma unroll
    for (int nt = 0; nt < 32; nt++)
        #pragma unroll
        for (int e = 0; e < 4; e++) O[nt][e] = 0.f;
    float mr0 = -1e30f, mr1 = -1e30f, lr0 = 0.f, lr1 = 0.f;

    for (int jt = 0; jt < NJT; jt++) {
        const int cur = jt & 1;
        CP_WAIT0();
        __syncthreads();
        if (jt + 1 < NJT) { load_tile(sm, n, (jt + 1) * BJ, 1 - cur, tid); CP_COMMIT(); }

        if (jt == 0) {
            #pragma unroll
            for (int kc = 0; kc < 2; kc++) {
                qh[kc][0] = QHw[(iw + g)     * 20 + 8 * kc + m];
                qh[kc][1] = QHw[(iw + g + 8) * 20 + 8 * kc + m];
                qh[kc][2] = QHw[(iw + g)     * 20 + 8 * kc + 4 + m];
                qh[kc][3] = QHw[(iw + g + 8) * 20 + 8 * kc + 4 + m];
                ql[kc][0] = QLw[(iw + g)     * 20 + 8 * kc + m];
                ql[kc][1] = QLw[(iw + g + 8) * 20 + 8 * kc + m];
                ql[kc][2] = QLw[(iw + g)     * 20 + 8 * kc + 4 + m];
                ql[kc][3] = QLw[(iw + g + 8) * 20 + 8 * kc + 4 + m];
            }
        }

        const uint32_t* KHw = (const uint32_t*)(sm + OFF_K + cur * 5120);
        const uint32_t* KLw = KHw + 640;
        const uint32_t* Vw  = (const uint32_t*)(sm + OFF_V + cur * 20480);

        // ---- S = Q K^T (3-term fp16 split) ----
        float C[4][4];
        #pragma unroll
        for (int nt = 0; nt < 4; nt++) {
            #pragma unroll
            for (int e = 0; e < 4; e++) C[nt][e] = 0.f;
            #pragma unroll
            for (int kc = 0; kc < 2; kc++) {
                uint32_t h0 = KHw[(8 * nt + g) * 20 + 8 * kc + m];
                uint32_t h1 = KHw[(8 * nt + g) * 20 + 8 * kc + 4 + m];
                uint32_t e0 = KLw[(8 * nt + g) * 20 + 8 * kc + m];
                uint32_t e1 = KLw[(8 * nt + g) * 20 + 8 * kc + 4 + m];
                mma_f16(C[nt], qh[kc], h0, h1);
                mma_f16(C[nt], ql[kc], h0, h1);
                mma_f16(C[nt], qh[kc], e0, e1);
            }
        }

        // ---- online softmax (fp16 P needs max-subtraction) ----
        float t0 = -1e30f, t1 = -1e30f;
        #pragma unroll
        for (int nt = 0; nt < 4; nt++) {
            t0 = fmaxf(t0, fmaxf(C[nt][0], C[nt][1]));
            t1 = fmaxf(t1, fmaxf(C[nt][2], C[nt][3]));
        }
        t0 = fmaxf(t0, __shfl_xor_sync(0xffffffffu, t0, 1));
        t0 = fmaxf(t0, __shfl_xor_sync(0xffffffffu, t0, 2));
        t1 = fmaxf(t1, __shfl_xor_sync(0xffffffffu, t1, 1));
        t1 = fmaxf(t1, __shfl_xor_sync(0xffffffffu, t1, 2));
        float mn0 = fmaxf(mr0, t0), mn1 = fmaxf(mr1, t1);
        float al0 = __expf(mr0 - mn0), al1 = __expf(mr1 - mn1);
        mr0 = mn0; mr1 = mn1;

        uint32_t P[4][2];
        float rs0 = 0.f, rs1 = 0.f;
        #pragma unroll
        for (int nt = 0; nt < 4; nt++) {
            float p0 = __expf(C[nt][0] - mn0), p1 = __expf(C[nt][1] - mn0);
            float p2 = __expf(C[nt][2] - mn1), p3 = __expf(C[nt][3] - mn1);
            __half2 h01 = __floats2half2_rn(p0, p1);
            __half2 h23 = __floats2half2_rn(p2, p3);
            P[nt][0] = h2u(h01); P[nt][1] = h2u(h23);
            float2 f01 = __half22float2(h01), f23 = __half22float2(h23);
            rs0 += f01.x + f01.y; rs1 += f23.x + f23.y;
        }
        rs0 += __shfl_xor_sync(0xffffffffu, rs0, 1);
        rs0 += __shfl_xor_sync(0xffffffffu, rs0, 2);
        rs1 += __shfl_xor_sync(0xffffffffu, rs1, 1);
        rs1 += __shfl_xor_sync(0xffffffffu, rs1, 2);
        lr0 = lr0 * al0 + rs0;
        lr1 = lr1 * al1 + rs1;

        if (__any_sync(0xffffffffu, (al0 != 1.f) || (al1 != 1.f))) {
            #pragma unroll
            for (int nt = 0; nt < 32; nt++) {
                O[nt][0] *= al0; O[nt][1] *= al0;
                O[nt][2] *= al1; O[nt][3] *= al1;
            }
        }

        // ---- O += P V (A-frag of P is a direct repack of the C-frags) ----
        #pragma unroll
        for (int kc = 0; kc < 2; kc++) {
            uint32_t pa[4] = { P[2 * kc][0], P[2 * kc][1], P[2 * kc + 1][0], P[2 * kc + 1][1] };
            #pragma unroll
            for (int nt = 0; nt < 32; nt++) {
                uint32_t v0 = Vw[(8 * nt + g) * 20 + 8 * kc + m];
                uint32_t v1 = Vw[(8 * nt + g) * 20 + 8 * kc + 4 + m];
                mma_f16(O[nt], pa, v0, v1);
            }
        }
    }

    // ---- epilogue ----
    const float linv0 = 1.0f / lr0;
    const float linv1 = 1.0f / lr1;
    const float gam = __ldg(gamma);
    #pragma unroll
    for (int nt = 0; nt < 32; nt++) {
        #pragma unroll
        for (int e = 0; e < 4; e++) {
            int c   = 8 * nt + 2 * m + (e & 1);
            int row = iw + g + 8 * (e >> 1);
            size_t idx = (((size_t)(n * CC + c)) << 12) + i0 + row;
            float o = O[nt][e] * ((e >> 1) ? linv1 : linv0);
            out[idx] = gam * o + __ldg(&x[idx]);
        }
    }
}

// ---------------- launch -----------------------------------------------------
extern "C" void kernel_launch(void* const* d_in, const int* in_sizes, int n_in,
                              void* d_out, int out_size) {
    const float* x     = (const float*)d_in[0];
    const float* Wq    = (const float*)d_in[1];
    const float* bq    = (const float*)d_in[2];
    const float* Wk    = (const float*)d_in[3];
    const float* bk    = (const float*)d_in[4];
    const float* Wv    = (const float*)d_in[5];
    const float* bv    = (const float*)d_in[6];
    const float* gamma = (const float*)d_in[7];
    float* out = (float*)d_out;

    cudaFuncSetAttribute(proj_kernel, cudaFuncAttributeMaxDynamicSharedMemorySize, 131072);
    cudaFuncSetAttribute(attn_kernel, cudaFuncAttributeMaxDynamicSharedMemorySize, ATTN_SMEM);

    wtrans_kernel<<<(320 * 256 + 255) / 256, 256>>>(Wq, Wk, Wv);
    proj_kernel<<<dim3(LL / 128, NB), 256, 131072>>>(x, bq, bk, bv);
    attn_kernel<<<dim3(LL / BI, NB), 128, ATTN_SMEM>>>(x, gamma, out);
}

// round 6
// speedup vs baseline: 2.9009x; 1.0120x over previous
#include <cuda_runtime.h>
#include <cuda_fp16.h>
#include <cstdint>

#define NB   8
#define CC   256
#define CQK  32
#define LL   4096
#define BI   64
#define BJ   32
#define NJT  (LL / BJ)          // 128 j-tiles
#define INVLN2 1.4426950408889634f

// ---------------- scratch (device globals) ----------------------------------
__device__ float  g_Wt [CC * 320];                  // fused weights, channel-major
__device__ __half g_qh [NB * LL * CQK];             // (N, L, 32) token-major fp16-hi
__device__ __half g_ql [NB * LL * CQK];
__device__ __half g_kh [NB * LL * CQK];             // (N, L, 32) token-major fp16-hi (scaled 1/ln2)
__device__ __half g_kl [NB * LL * CQK];
__device__ __half g_v  [(size_t)NB * CC * LL];      // (N, C, L) fp16, l contiguous

// ---------------- helpers ----------------------------------------------------
__device__ __forceinline__ uint32_t smem_u32(const void* p) {
    uint32_t a;
    asm("{ .reg .u64 t; cvta.to.shared.u64 t, %1; cvt.u32.u64 %0, t; }" : "=r"(a) : "l"(p));
    return a;
}
__device__ __forceinline__ void cp_async16(uint32_t dst, const void* src) {
    asm volatile("cp.async.cg.shared.global [%0], [%1], 16;"
                 :: "r"(dst), "l"((unsigned long long)__cvta_generic_to_global(src)) : "memory");
}
#define CP_COMMIT() asm volatile("cp.async.commit_group;" ::: "memory")
#define CP_WAIT0()  asm volatile("cp.async.wait_group 0;" ::: "memory")

__device__ __forceinline__ uint32_t h2u(__half2 h) { return *reinterpret_cast<uint32_t*>(&h); }
__device__ __forceinline__ float ex2f(float x) {
    float r;
    asm("ex2.approx.f32 %0, %1;" : "=f"(r) : "f"(x));
    return r;
}
__device__ __forceinline__ void ldsm_x4(uint32_t& r0, uint32_t& r1, uint32_t& r2, uint32_t& r3,
                                        uint32_t addr) {
    asm volatile("ldmatrix.sync.aligned.m8n8.x4.shared.b16 {%0,%1,%2,%3}, [%4];"
                 : "=r"(r0), "=r"(r1), "=r"(r2), "=r"(r3) : "r"(addr));
}
// m16n8k16 fp16 mma: D(f32) += A(f16) * B(f16)
__device__ __forceinline__ void mma_f16(float c[4], const uint32_t a[4],
                                        uint32_t b0, uint32_t b1) {
    asm("mma.sync.aligned.m16n8k16.row.col.f32.f16.f16.f32 "
        "{%0,%1,%2,%3}, {%4,%5,%6,%7}, {%8,%9}, {%0,%1,%2,%3};"
        : "+f"(c[0]), "+f"(c[1]), "+f"(c[2]), "+f"(c[3])
        : "r"(a[0]), "r"(a[1]), "r"(a[2]), "r"(a[3]), "r"(b0), "r"(b1));
}

// ---------------- kernel 1: weight transpose ---------------------------------
__global__ void wtrans_kernel(const float* __restrict__ Wq,
                              const float* __restrict__ Wk,
                              const float* __restrict__ Wv) {
    int idx = blockIdx.x * 256 + threadIdx.x;
    if (idx >= 320 * 256) return;
    int o = idx >> 8, c = idx & 255;
    float v;
    if (o < 32)       v = Wq[o * 256 + c];
    else if (o < 64)  v = Wk[(o - 32) * 256 + c];
    else              v = Wv[(o - 64) * 256 + c];
    g_Wt[c * 320 + o] = v;
}

// ---------------- kernel 2: fused QKV projection -----------------------------
__global__ __launch_bounds__(256, 1)
void proj_kernel(const float* __restrict__ x,
                 const float* __restrict__ bq,
                 const float* __restrict__ bk,
                 const float* __restrict__ bv) {
    extern __shared__ float xs[];   // [256][128]
    const int n  = blockIdx.y;
    const int l0 = blockIdx.x * 128;
    const int tid = threadIdx.x;

    const float* xb = x + ((size_t)n << 20) + l0;
    #pragma unroll 4
    for (int idx = tid; idx < 256 * 128; idx += 256) {
        int c = idx >> 7, l = idx & 127;
        xs[idx] = xb[(c << 12) + l];
    }
    __syncthreads();

    const int warp = tid >> 5, lane = tid & 31;
    const int lb = lane * 4;

    for (int og = 0; og < 10; og++) {
        const int obase = og * 32 + warp * 4;
        float bias[4];
        #pragma unroll
        for (int r = 0; r < 4; r++) {
            int o = obase + r;
            bias[r] = (o < 32) ? bq[o] : (o < 64) ? bk[o - 32] : bv[o - 64];
        }
        float4 acc0 = make_float4(bias[0], bias[0], bias[0], bias[0]);
        float4 acc1 = make_float4(bias[1], bias[1], bias[1], bias[1]);
        float4 acc2 = make_float4(bias[2], bias[2], bias[2], bias[2]);
        float4 acc3 = make_float4(bias[3], bias[3], bias[3], bias[3]);

        #pragma unroll 4
        for (int c = 0; c < 256; c++) {
            float4 w  = __ldg((const float4*)&g_Wt[c * 320 + obase]);
            float4 xv = *(const float4*)&xs[c * 128 + lb];
            acc0.x += w.x * xv.x; acc0.y += w.x * xv.y; acc0.z += w.x * xv.z; acc0.w += w.x * xv.w;
            acc1.x += w.y * xv.x; acc1.y += w.y * xv.y; acc1.z += w.y * xv.z; acc1.w += w.y * xv.w;
            acc2.x += w.z * xv.x; acc2.y += w.z * xv.y; acc2.z += w.z * xv.z; acc2.w += w.z * xv.w;
            acc3.x += w.w * xv.x; acc3.y += w.w * xv.y; acc3.z += w.w * xv.z; acc3.w += w.w * xv.w;
        }
        float4 acc[4] = {acc0, acc1, acc2, acc3};

        if (obase < 64) {
            const bool isQ = (obase < 32);
            __half* dsth = isQ ? g_qh : g_kh;
            __half* dstl = isQ ? g_ql : g_kl;
            const float sc = isQ ? 1.0f : INVLN2;   // K carries 1/ln2 -> exp2 domain
            const int ob = obase & 31;
            #pragma unroll
            for (int s = 0; s < 4; s++) {
                float v0 = (&acc[0].x)[s] * sc, v1 = (&acc[1].x)[s] * sc;
                float v2 = (&acc[2].x)[s] * sc, v3 = (&acc[3].x)[s] * sc;
                __half h0 = __float2half_rn(v0), h1 = __float2half_rn(v1);
                __half h2 = __float2half_rn(v2), h3 = __float2half_rn(v3);
                __half e0 = __float2half_rn(v0 - __half2float(h0));
                __half e1 = __float2half_rn(v1 - __half2float(h1));
                __half e2 = __float2half_rn(v2 - __half2float(h2));
                __half e3 = __float2half_rn(v3 - __half2float(h3));
                size_t base = ((size_t)((n << 12) + l0 + lb + s)) * 32 + ob;
                ((__half2*)(dsth + base))[0] = __halves2half2(h0, h1);
                ((__half2*)(dsth + base))[1] = __halves2half2(h2, h3);
                ((__half2*)(dstl + base))[0] = __halves2half2(e0, e1);
                ((__half2*)(dstl + base))[1] = __halves2half2(e2, e3);
            }
        } else {
            const int vo = obase - 64;
            #pragma unroll
            for (int r = 0; r < 4; r++) {
                float4 a = acc[r];
                size_t base = (((size_t)n * CC + vo + r) << 12) + l0 + lb;
                ((__half2*)(g_v + base))[0] = __floats2half2_rn(a.x, a.y);
                ((__half2*)(g_v + base))[1] = __floats2half2_rn(a.z, a.w);
            }
        }
    }
}

// ---------------- kernel 3: pipelined fp16 mma flash attention ---------------
// Rows padded to 40 fp16 (80 B) -> LDSM phases hit all 32 banks exactly once.
#define OFF_QH 0            // [64][40] fp16
#define OFF_QL 5120
#define OFF_K  10240        // 3 slots x 5120 B: [KH 32][40] then [KL 32][40]
#define OFF_V  25600        // 2 slots x 20480 B: [256][40] fp16
#define ATTN_SMEM 66560

__device__ __forceinline__ void loadK(uint32_t smb, int n, int j0, int slot, int tid) {
    const uint32_t kbase = smb + OFF_K + slot * 5120;
    #pragma unroll
    for (int it = 0; it < 2; it++) {
        int idx = it * 128 + tid;        // 0..255
        int hl = idx >> 7;
        int r  = (idx >> 2) & 31;
        int s  = idx & 3;
        const __half* src = (hl ? g_kl : g_kh) + ((size_t)((n << 12) + j0 + r)) * 32 + s * 8;
        cp_async16(kbase + hl * 2560 + r * 80 + s * 16, src);
    }
}
__device__ __forceinline__ void loadV(uint32_t smb, int n, int j0, int slot, int tid) {
    const uint32_t vbase = smb + OFF_V + slot * 20480;
    #pragma unroll
    for (int it = 0; it < 8; it++) {
        int idx = it * 128 + tid;        // 0..1023
        int cr = idx >> 2;
        int s  = idx & 3;
        const __half* src = g_v + (((size_t)n * CC + cr) << 12) + j0 + s * 8;
        cp_async16(vbase + cr * 80 + s * 16, src);
    }
}

__global__ __launch_bounds__(128, 2)
void attn_kernel(const float* __restrict__ x,
                 const float* __restrict__ gamma,
                 float* __restrict__ out) {
    extern __shared__ char sm[];
    const uint32_t smb = smem_u32(sm);
    const int tid  = threadIdx.x;
    const int wid  = tid >> 5, lane = tid & 31;
    const int g    = lane >> 2, m = lane & 3;
    const int iw   = wid * 16;
    const int n    = blockIdx.y;
    const int i0   = blockIdx.x * BI;

    // per-lane ldmatrix offset: quad q=lane>>3 selects (kc, b0/b1) column group
    const uint32_t aoff = (uint32_t)((lane & 7) * 80 + (lane >> 3) * 16);

    // ---- prologue: Q + K(0) + K(1) + V(0), one commit group ----
    #pragma unroll
    for (int it = 0; it < 4; it++) {
        int idx  = it * 128 + tid;          // 0..511
        int half = idx >> 8;
        int r    = (idx >> 2) & 63;
        int s    = idx & 3;
        const __half* src = (half ? g_ql : g_qh) + ((size_t)((n << 12) + i0 + r)) * 32 + s * 8;
        cp_async16(smb + (half ? OFF_QL : OFF_QH) + r * 80 + s * 16, src);
    }
    loadK(smb, n, 0, 0, tid);
    loadK(smb, n, BJ, 1, tid);
    loadV(smb, n, 0, 0, tid);
    CP_COMMIT();

    uint32_t qh[2][4], ql[2][4];
    float O[32][4];
    #pragma unroll
    for (int nt = 0; nt < 32; nt++)
        #pragma unroll
        for (int e = 0; e < 4; e++) O[nt][e] = 0.f;
    float mr0 = -1e30f, mr1 = -1e30f, lr0 = 0.f, lr1 = 0.f;

    float Cb[2][4][4];
    int ks_next = 1;   // K slot of tile jt+1

    #pragma unroll 2
    for (int jt = 0; jt < NJT; jt++) {
        CP_WAIT0();
        __syncthreads();
        // prefetch K(jt+2), V(jt+1)
        if (jt + 2 < NJT) {
            int ks2 = ks_next + 1; if (ks2 == 3) ks2 = 0;
            loadK(smb, n, (jt + 2) * BJ, ks2, tid);
        }
        if (jt + 1 < NJT) loadV(smb, n, (jt + 1) * BJ, 1 - (jt & 1), tid);
        CP_COMMIT();

        if (jt == 0) {
            // Q fragments (once)
            const uint32_t* QHw = (const uint32_t*)(sm + OFF_QH);
            const uint32_t* QLw = (const uint32_t*)(sm + OFF_QL);
            #pragma unroll
            for (int kc = 0; kc < 2; kc++) {
                qh[kc][0] = QHw[(iw + g)     * 20 + 8 * kc + m];
                qh[kc][1] = QHw[(iw + g + 8) * 20 + 8 * kc + m];
                qh[kc][2] = QHw[(iw + g)     * 20 + 8 * kc + 4 + m];
                qh[kc][3] = QHw[(iw + g + 8) * 20 + 8 * kc + 4 + m];
                ql[kc][0] = QLw[(iw + g)     * 20 + 8 * kc + m];
                ql[kc][1] = QLw[(iw + g + 8) * 20 + 8 * kc + m];
                ql[kc][2] = QLw[(iw + g)     * 20 + 8 * kc + 4 + m];
                ql[kc][3] = QLw[(iw + g + 8) * 20 + 8 * kc + 4 + m];
            }
            // S(0) into Cb[0] from K slot 0
            const uint32_t kb = smb + OFF_K + 0 * 5120;
            #pragma unroll
            for (int nt = 0; nt < 4; nt++) {
                float* C = Cb[0][nt];
                C[0] = C[1] = C[2] = C[3] = 0.f;
                uint32_t h0, h1, h2, h3, e0, e1, e2, e3;
                ldsm_x4(h0, h1, h2, h3, kb + nt * 640 + aoff);
                ldsm_x4(e0, e1, e2, e3, kb + 2560 + nt * 640 + aoff);
                mma_f16(C, qh[0], h0, h1);  mma_f16(C, ql[0], h0, h1);  mma_f16(C, qh[0], e0, e1);
                mma_f16(C, qh[1], h2, h3);  mma_f16(C, ql[1], h2, h3);  mma_f16(C, qh[1], e2, e3);
            }
        }

        // ---- S(jt+1) into the other C buffer (overlaps softmax below) ----
        if (jt + 1 < NJT) {
            const uint32_t kb = smb + OFF_K + ks_next * 5120;
            #pragma unroll
            for (int nt = 0; nt < 4; nt++) {
                float* C = Cb[(jt + 1) & 1][nt];
                C[0] = C[1] = C[2] = C[3] = 0.f;
                uint32_t h0, h1, h2, h3, e0, e1, e2, e3;
                ldsm_x4(h0, h1, h2, h3, kb + nt * 640 + aoff);
                ldsm_x4(e0, e1, e2, e3, kb + 2560 + nt * 640 + aoff);
                mma_f16(C, qh[0], h0, h1);  mma_f16(C, ql[0], h0, h1);  mma_f16(C, qh[0], e0, e1);
                mma_f16(C, qh[1], h2, h3);  mma_f16(C, ql[1], h2, h3);  mma_f16(C, qh[1], e2, e3);
            }
            if (++ks_next == 3) ks_next = 0;
        }

        // ---- softmax(jt) in exp2 domain ----
        float (*C)[4] = Cb[jt & 1];
        float t0 = -1e30f, t1 = -1e30f;
        #pragma unroll
        for (int nt = 0; nt < 4; nt++) {
            t0 = fmaxf(t0, fmaxf(C[nt][0], C[nt][1]));
            t1 = fmaxf(t1, fmaxf(C[nt][2], C[nt][3]));
        }
        t0 = fmaxf(t0, __shfl_xor_sync(0xffffffffu, t0, 1));
        t0 = fmaxf(t0, __shfl_xor_sync(0xffffffffu, t0, 2));
        t1 = fmaxf(t1, __shfl_xor_sync(0xffffffffu, t1, 1));
        t1 = fmaxf(t1, __shfl_xor_sync(0xffffffffu, t1, 2));
        float mn0 = fmaxf(mr0, t0), mn1 = fmaxf(mr1, t1);
        float al0 = ex2f(mr0 - mn0), al1 = ex2f(mr1 - mn1);
        mr0 = mn0; mr1 = mn1;

        uint32_t P[4][2];
        float rs0 = 0.f, rs1 = 0.f;
        #pragma unroll
        for (int nt = 0; nt < 4; nt++) {
            float p0 = ex2f(C[nt][0] - mn0), p1 = ex2f(C[nt][1] - mn0);
            float p2 = ex2f(C[nt][2] - mn1), p3 = ex2f(C[nt][3] - mn1);
            __half2 h01 = __floats2half2_rn(p0, p1);
            __half2 h23 = __floats2half2_rn(p2, p3);
            P[nt][0] = h2u(h01); P[nt][1] = h2u(h23);
            float2 f01 = __half22float2(h01), f23 = __half22float2(h23);
            rs0 += f01.x + f01.y; rs1 += f23.x + f23.y;
        }
        rs0 += __shfl_xor_sync(0xffffffffu, rs0, 1);
        rs0 += __shfl_xor_sync(0xffffffffu, rs0, 2);
        rs1 += __shfl_xor_sync(0xffffffffu, rs1, 1);
        rs1 += __shfl_xor_sync(0xffffffffu, rs1, 2);
        lr0 = lr0 * al0 + rs0;
        lr1 = lr1 * al1 + rs1;

        if (__any_sync(0xffffffffu, (al0 != 1.f) || (al1 != 1.f))) {
            #pragma unroll
            for (int nt = 0; nt < 32; nt++) {
                O[nt][0] *= al0; O[nt][1] *= al0;
                O[nt][2] *= al1; O[nt][3] *= al1;
            }
        }

        // ---- O += P V  (ldmatrix.x4 per nt: 4 B-frags in one op) ----
        uint32_t pa0[4] = { P[0][0], P[0][1], P[1][0], P[1][1] };
        uint32_t pa1[4] = { P[2][0], P[2][1], P[3][0], P[3][1] };
        const uint32_t vb = smb + OFF_V + (jt & 1) * 20480;
        #pragma unroll
        for (int nt = 0; nt < 32; nt++) {
            uint32_t b00, b01, b10, b11;
            ldsm_x4(b00, b01, b10, b11, vb + nt * 640 + aoff);
            mma_f16(O[nt], pa0, b00, b01);
            mma_f16(O[nt], pa1, b10, b11);
        }
    }

    // ---- epilogue ----
    const float linv0 = 1.0f / lr0;
    const float linv1 = 1.0f / lr1;
    const float gam = __ldg(gamma);
    #pragma unroll
    for (int nt = 0; nt < 32; nt++) {
        #pragma unroll
        for (int e = 0; e < 4; e++) {
            int c   = 8 * nt + 2 * m + (e & 1);
            int row = iw + g + 8 * (e >> 1);
            size_t idx = (((size_t)(n * CC + c)) << 12) + i0 + row;
            float o = O[nt][e] * ((e >> 1) ? linv1 : linv0);
            out[idx] = gam * o + __ldg(&x[idx]);
        }
    }
}

// ---------------- launch -----------------------------------------------------
extern "C" void kernel_launch(void* const* d_in, const int* in_sizes, int n_in,
                              void* d_out, int out_size) {
    const float* x     = (const float*)d_in[0];
    const float* Wq    = (const float*)d_in[1];
    const float* bq    = (const float*)d_in[2];
    const float* Wk    = (const float*)d_in[3];
    const float* bk    = (const float*)d_in[4];
    const float* Wv    = (const float*)d_in[5];
    const float* bv    = (const float*)d_in[6];
    const float* gamma = (const float*)d_in[7];
    float* out = (float*)d_out;

    cudaFuncSetAttribute(proj_kernel, cudaFuncAttributeMaxDynamicSharedMemorySize, 131072);
    cudaFuncSetAttribute(attn_kernel, cudaFuncAttributeMaxDynamicSharedMemorySize, ATTN_SMEM);

    wtrans_kernel<<<(320 * 256 + 255) / 256, 256>>>(Wq, Wk, Wv);
    proj_kernel<<<dim3(LL / 128, NB), 256, 131072>>>(x, bq, bk, bv);
    attn_kernel<<<dim3(LL / BI, NB), 128, ATTN_SMEM>>>(x, gamma, out);
}